// round 14
// baseline (speedup 1.0000x reference)
#include <cuda_runtime.h>

// ARModel: self-feeding AR(P), k=6 linearized expansion + f32x2 node packing.
//
// pred_{t+m} = c^m . h_t + beta_m * bias   (m = 0..5)
//   c^0 = a;  c^{m+1}[0] = c^m[11]*a[0];  c^{m+1}[j] = c^m[11]*a[j] + c^m[j-1]
//   beta_0 = 1;  beta_{m+1} = beta_m + c^m[11]
// Each phase emits 6 predictions from one window -> 72 FFMA2 spanning 6
// independent accumulation chains; chain latency is fully hidden inside the
// phase's own issue time even with ~1.7 warps/SMSP.
//
// Thread handles two adjacent nodes packed in f32x2 lanes; all global traffic
// is 8-byte and warp-coalesced.

constexpr int Bd = 64;
constexpr int Td = 288;
constexpr int Nd = 1024;
constexpr int Pd = 12;
constexpr int K  = 6;              // steps per phase
static_assert(Td % Pd == 0 && Pd % K == 0, "unroll structure");

typedef unsigned long long u64;

__device__ __forceinline__ u64 pack2(float lo, float hi) {
    u64 r; asm("mov.b64 %0, {%1, %2};" : "=l"(r) : "f"(lo), "f"(hi)); return r;
}
__device__ __forceinline__ u64 fma2(u64 a, u64 b, u64 c) {
    u64 d; asm("fma.rn.f32x2 %0, %1, %2, %3;" : "=l"(d) : "l"(a), "l"(b), "l"(c)); return d;
}

__global__ void __launch_bounds__(32)
ar_model_k6_kernel(const float* __restrict__ x,
                   const float* __restrict__ ar,
                   const float* __restrict__ bias,
                   float* __restrict__ out)
{
    const int tid = blockIdx.x * 32 + threadIdx.x;   // 0 .. 32767
    const int b   = tid >> 9;                        // batch
    const int pr  = tid & 511;                       // node pair
    const int n0  = pr * 2;

    // ---- scalar prologue: expanded coefficient rows for both lanes ----
    // clo/chi[m][j] = (a M^m)[j]; computed in scalar fp32, then packed.
    float clo[K][Pd], chi[K][Pd];
#pragma unroll
    for (int j = 0; j < Pd; ++j) {
        clo[0][j] = ar[n0 * Pd + j];
        chi[0][j] = ar[(n0 + 1) * Pd + j];
    }
#pragma unroll
    for (int m = 1; m < K; ++m) {
        const float tl = clo[m - 1][Pd - 1], th = chi[m - 1][Pd - 1];
        clo[m][0] = tl * clo[0][0];
        chi[m][0] = th * chi[0][0];
#pragma unroll
        for (int j = 1; j < Pd; ++j) {
            clo[m][j] = fmaf(tl, clo[0][j], clo[m - 1][j - 1]);
            chi[m][j] = fmaf(th, chi[0][j], chi[m - 1][j - 1]);
        }
    }

    // beta_m = 1 + sum_{i<m} c^i[11];  bb_m = beta_m * bias (per lane)
    const float blo = bias[n0], bhi = bias[n0 + 1];
    u64 bb[K];
    {
        float betl = 1.0f, beth = 1.0f;
        bb[0] = pack2(blo, bhi);
#pragma unroll
        for (int m = 1; m < K; ++m) {
            betl += clo[m - 1][Pd - 1];
            beth += chi[m - 1][Pd - 1];
            bb[m] = pack2(betl * blo, beth * bhi);
        }
    }

    // pack coefficient rows
    u64 c[K][Pd];
#pragma unroll
    for (int m = 0; m < K; ++m)
#pragma unroll
        for (int j = 0; j < Pd; ++j) c[m][j] = pack2(clo[m][j], chi[m][j]);

    // ---- initial history window (oldest first) ----
    u64 buf[Pd];
    const u64* xr = reinterpret_cast<const u64*>(
        x + ((size_t)b * Td + (Td - Pd)) * Nd + n0);
#pragma unroll
    for (int j = 0; j < Pd; ++j) buf[j] = xr[(size_t)j * (Nd / 2)];

    u64* o = reinterpret_cast<u64*>(out + (size_t)b * Td * Nd + n0);
    constexpr int ST = Nd / 2;                       // timestep stride in u64

    for (int r = 0; r < Td / Pd; ++r) {              // 24 rounds x 12 steps
#pragma unroll
        for (int ph = 0; ph < Pd / K; ++ph) {        // 2 phases, off = 0, 6
            const int off = ph * K;
            u64 p[K];
#pragma unroll
            for (int m = 0; m < K; ++m) p[m] = bb[m];
#pragma unroll
            for (int j = 0; j < Pd; ++j) {
                const u64 h = buf[(off + j) % Pd];   // constant index post-unroll
#pragma unroll
                for (int m = 0; m < K; ++m)
                    p[m] = fma2(c[m][j], h, p[m]);
            }
#pragma unroll
            for (int m = 0; m < K; ++m) {
                buf[off + m] = p[m];                 // replace 6 oldest slots
                o[(size_t)(off + m) * ST] = p[m];    // compile-time offsets
            }
        }
        o += (size_t)Pd * ST;                        // one pointer bump / round
    }
}

extern "C" void kernel_launch(void* const* d_in, const int* in_sizes, int n_in,
                              void* d_out, int out_size)
{
    const float* x    = (const float*)d_in[0];  // (B, T, N, 1) fp32
    const float* ar   = (const float*)d_in[1];  // (N, P) fp32
    const float* bias = (const float*)d_in[2];  // (N,) fp32
    float* out = (float*)d_out;

    // 64 * 512 node-pairs = 32768 threads in 32-thread blocks -> 1024 blocks.
    ar_model_k6_kernel<<<(Bd * (Nd / 2)) / 32, 32>>>(x, ar, bias, out);
}

// round 15
// speedup vs baseline: 1.0019x; 1.0019x over previous
#include <cuda_runtime.h>

// ARModel: self-feeding AR(P), k=6 linearized expansion + f32x2 node packing.
//
// pred_{t+m} = c^m . h_t + beta_m * bias   (m = 0..5)
//   c^0 = a;  c^{m+1}[0] = c^m[11]*a[0];  c^{m+1}[j] = c^m[11]*a[j] + c^m[j-1]
//   beta_0 = 1;  beta_{m+1} = beta_m + c^m[11]
// Each phase emits 6 predictions from one window -> 72 FFMA2 spanning 6
// independent accumulation chains; chain latency is fully hidden inside the
// phase's own issue time even with ~1.7 warps/SMSP.
//
// Thread handles two adjacent nodes packed in f32x2 lanes; all global traffic
// is 8-byte and warp-coalesced.

constexpr int Bd = 64;
constexpr int Td = 288;
constexpr int Nd = 1024;
constexpr int Pd = 12;
constexpr int K  = 6;              // steps per phase
static_assert(Td % Pd == 0 && Pd % K == 0, "unroll structure");

typedef unsigned long long u64;

__device__ __forceinline__ u64 pack2(float lo, float hi) {
    u64 r; asm("mov.b64 %0, {%1, %2};" : "=l"(r) : "f"(lo), "f"(hi)); return r;
}
__device__ __forceinline__ u64 fma2(u64 a, u64 b, u64 c) {
    u64 d; asm("fma.rn.f32x2 %0, %1, %2, %3;" : "=l"(d) : "l"(a), "l"(b), "l"(c)); return d;
}

__global__ void __launch_bounds__(32)
ar_model_k6_kernel(const float* __restrict__ x,
                   const float* __restrict__ ar,
                   const float* __restrict__ bias,
                   float* __restrict__ out)
{
    const int tid = blockIdx.x * 32 + threadIdx.x;   // 0 .. 32767
    const int b   = tid >> 9;                        // batch
    const int pr  = tid & 511;                       // node pair
    const int n0  = pr * 2;

    // ---- scalar prologue: expanded coefficient rows for both lanes ----
    // clo/chi[m][j] = (a M^m)[j]; computed in scalar fp32, then packed.
    float clo[K][Pd], chi[K][Pd];
#pragma unroll
    for (int j = 0; j < Pd; ++j) {
        clo[0][j] = ar[n0 * Pd + j];
        chi[0][j] = ar[(n0 + 1) * Pd + j];
    }
#pragma unroll
    for (int m = 1; m < K; ++m) {
        const float tl = clo[m - 1][Pd - 1], th = chi[m - 1][Pd - 1];
        clo[m][0] = tl * clo[0][0];
        chi[m][0] = th * chi[0][0];
#pragma unroll
        for (int j = 1; j < Pd; ++j) {
            clo[m][j] = fmaf(tl, clo[0][j], clo[m - 1][j - 1]);
            chi[m][j] = fmaf(th, chi[0][j], chi[m - 1][j - 1]);
        }
    }

    // beta_m = 1 + sum_{i<m} c^i[11];  bb_m = beta_m * bias (per lane)
    const float blo = bias[n0], bhi = bias[n0 + 1];
    u64 bb[K];
    {
        float betl = 1.0f, beth = 1.0f;
        bb[0] = pack2(blo, bhi);
#pragma unroll
        for (int m = 1; m < K; ++m) {
            betl += clo[m - 1][Pd - 1];
            beth += chi[m - 1][Pd - 1];
            bb[m] = pack2(betl * blo, beth * bhi);
        }
    }

    // pack coefficient rows
    u64 c[K][Pd];
#pragma unroll
    for (int m = 0; m < K; ++m)
#pragma unroll
        for (int j = 0; j < Pd; ++j) c[m][j] = pack2(clo[m][j], chi[m][j]);

    // ---- initial history window (oldest first) ----
    u64 buf[Pd];
    const u64* xr = reinterpret_cast<const u64*>(
        x + ((size_t)b * Td + (Td - Pd)) * Nd + n0);
#pragma unroll
    for (int j = 0; j < Pd; ++j) buf[j] = xr[(size_t)j * (Nd / 2)];

    u64* o = reinterpret_cast<u64*>(out + (size_t)b * Td * Nd + n0);
    constexpr int ST = Nd / 2;                       // timestep stride in u64

    for (int r = 0; r < Td / Pd; ++r) {              // 24 rounds x 12 steps
#pragma unroll
        for (int ph = 0; ph < Pd / K; ++ph) {        // 2 phases, off = 0, 6
            const int off = ph * K;
            u64 p[K];
#pragma unroll
            for (int m = 0; m < K; ++m) p[m] = bb[m];
#pragma unroll
            for (int j = 0; j < Pd; ++j) {
                const u64 h = buf[(off + j) % Pd];   // constant index post-unroll
#pragma unroll
                for (int m = 0; m < K; ++m)
                    p[m] = fma2(c[m][j], h, p[m]);
            }
#pragma unroll
            for (int m = 0; m < K; ++m) {
                buf[off + m] = p[m];                 // replace 6 oldest slots
                o[(size_t)(off + m) * ST] = p[m];    // compile-time offsets
            }
        }
        o += (size_t)Pd * ST;                        // one pointer bump / round
    }
}

extern "C" void kernel_launch(void* const* d_in, const int* in_sizes, int n_in,
                              void* d_out, int out_size)
{
    const float* x    = (const float*)d_in[0];  // (B, T, N, 1) fp32
    const float* ar   = (const float*)d_in[1];  // (N, P) fp32
    const float* bias = (const float*)d_in[2];  // (N,) fp32
    float* out = (float*)d_out;

    // 64 * 512 node-pairs = 32768 threads in 32-thread blocks -> 1024 blocks.
    ar_model_k6_kernel<<<(Bd * (Nd / 2)) / 32, 32>>>(x, ar, bias, out);
}